// round 5
// baseline (speedup 1.0000x reference)
#include <cuda_runtime.h>
#include <math.h>

#define Tn   64
#define Bn   16
#define Nn   256
#define Wn   64
#define Rn   4
#define INn  64
#define IFS  471
#define IFP  472
#define EPSf 1e-6f
#define NT   256

// global scratch (allocation-free)
__device__ float g_link[Bn * Nn * Nn];   // 4 MB, L2-resident; lk[row*256+col]
__device__ float g_Wifp[256 * IFP];      // W_if repacked pitch 471 -> 472

struct SMem {
    float  mem[Nn][Wn + 1];          // pitch 65, conflict-free
    float4 Lst[32 * 65];             // staging tile for fwd pass
    float4 scratch4[256];
    float4 fwdv[Nn];
    float4 bwdv[Nn];
    float4 rcv[Nn];
    float4 rwv[Nn];
    float4 keyn4[Wn];
    float  rvec[256];
    float  ctrl[INn + 256];
    float  h[256];
    float  nn[256];
    float  z[IFP];
    float  ww[Nn];
    float  prec[Nn];
    float  usage[Nn];
    float  alloc_[Nn];
    unsigned long long skey[Nn];
    float  scanp[Nn];
    float  wkeyn[Wn];
    float  er[Wn];
    float  wv[Wn];
    float  wc[Nn];
    float  red[40];
    float  rstr[Rn];
    float  freeg[Rn];
    float  modes[3][Rn];
    float  wstr, allocg, writeg;
};

__device__ __forceinline__ float sigm_(float x) { return 1.0f / (1.0f + expf(-x)); }
__device__ __forceinline__ float softp_(float x) { return fmaxf(x, 0.0f) + log1pf(expf(-fabsf(x))); }

__device__ __forceinline__ float bsum(float* red, float v, int tid) {
#pragma unroll
    for (int o = 16; o; o >>= 1) v += __shfl_xor_sync(0xffffffffu, v, o);
    if ((tid & 31) == 0) red[tid >> 5] = v;
    __syncthreads();
    if (tid == 0) {
        float a = red[0];
#pragma unroll
        for (int i = 1; i < 8; ++i) a += red[i];
        red[36] = a;
    }
    __syncthreads();
    return red[36];
}
__device__ __forceinline__ float bmax(float* red, float v, int tid) {
#pragma unroll
    for (int o = 16; o; o >>= 1) v = fmaxf(v, __shfl_xor_sync(0xffffffffu, v, o));
    if ((tid & 31) == 0) red[tid >> 5] = v;
    __syncthreads();
    if (tid == 0) {
        float a = red[0];
#pragma unroll
        for (int i = 1; i < 8; ++i) a = fmaxf(a, red[i]);
        red[36] = a;
    }
    __syncthreads();
    return red[36];
}
// 4-wide block reduction: v[0..3] replaced with block-reduced values
__device__ __forceinline__ void bred4(float* red, float* v, int tid, int domax) {
#pragma unroll
    for (int o = 16; o; o >>= 1) {
#pragma unroll
        for (int r = 0; r < 4; ++r) {
            float w = __shfl_xor_sync(0xffffffffu, v[r], o);
            v[r] = domax ? fmaxf(v[r], w) : (v[r] + w);
        }
    }
    if ((tid & 31) == 0) {
#pragma unroll
        for (int r = 0; r < 4; ++r) red[(tid >> 5) * 4 + r] = v[r];
    }
    __syncthreads();
    if (tid < 4) {
        float a = red[tid];
#pragma unroll
        for (int w = 1; w < 8; ++w) {
            float b = red[w * 4 + tid];
            a = domax ? fmaxf(a, b) : (a + b);
        }
        red[32 + tid] = a;
    }
    __syncthreads();
#pragma unroll
    for (int r = 0; r < 4; ++r) v[r] = red[32 + r];
}

__global__ void repack_kernel(const float* __restrict__ Wif) {
    int i = blockIdx.x;
    int j = threadIdx.x;
    if (j < IFP) g_Wifp[i * IFP + j] = (j < IFS) ? Wif[i * IFS + j] : 0.0f;
}

__global__ void __launch_bounds__(NT, 1)
dnc_kernel(const float* __restrict__ x, const float* __restrict__ W1,
           const float* __restrict__ b1, const float* __restrict__ W2,
           const float* __restrict__ b2, const float* __restrict__ bif,
           const float* __restrict__ Wout, const float* __restrict__ Wmem,
           float* __restrict__ out) {
    extern __shared__ char smraw[];
    SMem* s = (SMem*)smraw;
    const int tid = threadIdx.x;
    const int b = blockIdx.x;
    float* lk = g_link + b * (Nn * Nn);

    // init carries
    {
        float4 z4 = make_float4(0.f, 0.f, 0.f, 0.f);
        for (int i = tid; i < Nn * Nn / 4; i += NT) ((float4*)lk)[i] = z4;
#pragma unroll 8
        for (int w = 0; w < Wn; ++w) s->mem[tid][w] = EPSf;
        s->usage[tid] = 0.0f;
        s->ww[tid] = 0.0f;
        s->prec[tid] = 0.0f;
        s->rwv[tid] = z4;
        s->rvec[tid] = 0.0f;
    }
    __syncthreads();

    float* sc = (float*)s->scratch4;

    for (int t = 0; t < Tn; ++t) {
        // P1: controller input
        if (tid < INn) s->ctrl[tid] = x[(t * Bn + b) * INn + tid];
        s->ctrl[INn + tid] = s->rvec[tid];
        __syncthreads();

        // P2: h = tanh(ctrl @ W1 + b1), 320x256
        {
            int sg = tid >> 6, q = tid & 63;
            const float4* Wp = (const float4*)W1;
            float4 acc = make_float4(0.f, 0.f, 0.f, 0.f);
            int i0 = sg * 80;
#pragma unroll 4
            for (int i = i0; i < i0 + 80; ++i) {
                float c = s->ctrl[i];
                float4 w4 = Wp[i * 64 + q];
                acc.x = fmaf(c, w4.x, acc.x); acc.y = fmaf(c, w4.y, acc.y);
                acc.z = fmaf(c, w4.z, acc.z); acc.w = fmaf(c, w4.w, acc.w);
            }
            s->scratch4[sg * 64 + q] = acc;
        }
        __syncthreads();
        {
            int q = tid >> 2, c = tid & 3;
            float v = b1[tid];
#pragma unroll
            for (int sg = 0; sg < 4; ++sg) v += sc[(sg * 64 + q) * 4 + c];
            s->h[tid] = tanhf(v);
        }
        __syncthreads();

        // P3: nn = tanh(h @ W2 + b2), 256x256
        {
            int sg = tid >> 6, q = tid & 63;
            const float4* Wp = (const float4*)W2;
            float4 acc = make_float4(0.f, 0.f, 0.f, 0.f);
            int i0 = sg * 64;
#pragma unroll 4
            for (int i = i0; i < i0 + 64; ++i) {
                float c = s->h[i];
                float4 w4 = Wp[i * 64 + q];
                acc.x = fmaf(c, w4.x, acc.x); acc.y = fmaf(c, w4.y, acc.y);
                acc.z = fmaf(c, w4.z, acc.z); acc.w = fmaf(c, w4.w, acc.w);
            }
            s->scratch4[sg * 64 + q] = acc;
        }
        __syncthreads();
        {
            int q = tid >> 2, c = tid & 3;
            float v = b2[tid];
#pragma unroll
            for (int sg = 0; sg < 4; ++sg) v += sc[(sg * 64 + q) * 4 + c];
            s->nn[tid] = tanhf(v);
        }
        __syncthreads();

        // P4: z = nn @ W_if + b_if, 256x471 (packed pitch 472)
        {   // round A: outputs 0..255
            int sg = tid >> 6, q = tid & 63;
            const float4* Wp = (const float4*)g_Wifp;
            float4 acc = make_float4(0.f, 0.f, 0.f, 0.f);
            int i0 = sg * 64;
#pragma unroll 4
            for (int i = i0; i < i0 + 64; ++i) {
                float c = s->nn[i];
                float4 w4 = Wp[i * 118 + q];
                acc.x = fmaf(c, w4.x, acc.x); acc.y = fmaf(c, w4.y, acc.y);
                acc.z = fmaf(c, w4.z, acc.z); acc.w = fmaf(c, w4.w, acc.w);
            }
            s->scratch4[sg * 64 + q] = acc;
        }
        __syncthreads();
        {
            int q = tid >> 2, c = tid & 3;
            float v = bif[tid];
#pragma unroll
            for (int sg = 0; sg < 4; ++sg) v += sc[(sg * 64 + q) * 4 + c];
            s->z[tid] = v;
        }
        __syncthreads();
        {   // round B: outputs 256..470
            int sg = tid >> 6, q0 = tid & 63;
            if (q0 < 54) {
                const float4* Wp = (const float4*)g_Wifp;
                float4 acc = make_float4(0.f, 0.f, 0.f, 0.f);
                int i0 = sg * 64, q = 64 + q0;
#pragma unroll 4
                for (int i = i0; i < i0 + 64; ++i) {
                    float c = s->nn[i];
                    float4 w4 = Wp[i * 118 + q];
                    acc.x = fmaf(c, w4.x, acc.x); acc.y = fmaf(c, w4.y, acc.y);
                    acc.z = fmaf(c, w4.z, acc.z); acc.w = fmaf(c, w4.w, acc.w);
                }
                s->scratch4[sg * 64 + q0] = acc;
            }
        }
        __syncthreads();
        if (tid < 215) {
            int j = 256 + tid;
            int qb = (j >> 2) - 64, c = j & 3;
            float v = bif[j];
#pragma unroll
            for (int sg = 0; sg < 4; ++sg) v += sc[(sg * 64 + qb) * 4 + c];
            s->z[j] = v;
        }
        __syncthreads();

        // P5: parse interface
        if (tid < Rn) s->rstr[tid] = 1.0f + softp_(s->z[256 + tid]);
        if (tid >= 4 && tid < 8) s->freeg[tid - 4] = sigm_(s->z[453 + (tid - 4)]);
        if (tid == 8)  s->wstr   = 1.0f + softp_(s->z[324]);
        if (tid == 9)  s->allocg = sigm_(s->z[457]);
        if (tid == 10) s->writeg = sigm_(s->z[458]);
        if (tid >= 64 && tid < 128) {
            int w = tid - 64;
            s->er[w] = sigm_(s->z[325 + w]);
            s->wv[w] = s->z[389 + w];
        }
        if (tid >= 16 && tid < 20) {  // read key inverse norms (per r, over w)
            int r = tid - 16;
            float s2 = 0.f;
#pragma unroll 8
            for (int w = 0; w < Wn; ++w) { float v = s->z[w * 4 + r]; s2 = fmaf(v, v, s2); }
            s->red[32 + r] = 1.0f / (sqrtf(s2) + EPSf);
        }
        if (tid == 20) {  // write key inverse norm
            float s2 = 0.f;
#pragma unroll 8
            for (int w = 0; w < Wn; ++w) { float v = s->z[260 + w]; s2 = fmaf(v, v, s2); }
            s->red[38] = 1.0f / (sqrtf(s2) + EPSf);
        }
        if (tid >= 24 && tid < 28) {  // read-mode softmax over 3
            int r = tid - 24;
            float a = s->z[459 + r], bm = s->z[463 + r], c = s->z[467 + r];
            float mx = fmaxf(a, fmaxf(bm, c));
            float ea = expf(a - mx), eb = expf(bm - mx), ec = expf(c - mx);
            float si = 1.0f / (ea + eb + ec);
            s->modes[0][r] = ea * si; s->modes[1][r] = eb * si; s->modes[2][r] = ec * si;
        }
        __syncthreads();
        ((float*)s->keyn4)[tid] = s->z[tid] * s->red[32 + (tid & 3)] * s->rstr[tid & 3];
        if (tid < Wn) s->wkeyn[tid] = s->z[260 + tid] * s->red[38] * s->wstr;
        __syncthreads();

        // P6: retention + usage (old ww, old rw) + write-content sim (old mem)
        {
            float4 rw4 = s->rwv[tid];
            float ret = (1.f - s->freeg[0] * rw4.x) * (1.f - s->freeg[1] * rw4.y) *
                        (1.f - s->freeg[2] * rw4.z) * (1.f - s->freeg[3] * rw4.w);
            float u = s->usage[tid], w0 = s->ww[tid];
            u = (u + w0 - u * w0) * ret;
            s->usage[tid] = u;
            s->skey[tid] = ((unsigned long long)__float_as_uint(u) << 32) | (unsigned int)tid;
            float nrm = 0.f, dot = 0.f;
#pragma unroll 8
            for (int w = 0; w < Wn; ++w) {
                float m = s->mem[tid][w];
                nrm = fmaf(m, m, nrm);
                dot = fmaf(m, s->wkeyn[w], dot);
            }
            s->wc[tid] = dot / (sqrtf(nrm) + EPSf);
        }
        __syncthreads();
        {   // write-content softmax over n
            float v = s->wc[tid];
            float mx = bmax(s->red, v, tid);
            float e = expf(v - mx);
            float sm = bsum(s->red, e, tid);
            s->wc[tid] = e / sm;
        }

        // P7: allocation (stable argsort via bitonic on packed keys + cumprod)
        for (int k = 2; k <= 256; k <<= 1) {
            for (int j = k >> 1; j > 0; j >>= 1) {
                int i = tid, ixj = i ^ j;
                if (ixj > i) {
                    unsigned long long a = s->skey[i], bb = s->skey[ixj];
                    bool up = ((i & k) == 0);
                    if ((a > bb) == up) { s->skey[i] = bb; s->skey[ixj] = a; }
                }
                __syncthreads();
            }
        }
        s->scanp[tid] = __uint_as_float((unsigned int)(s->skey[tid] >> 32));
        __syncthreads();
        for (int d = 1; d < 256; d <<= 1) {
            float a = s->scanp[tid];
            float m = (tid >= d) ? s->scanp[tid - d] : 1.0f;
            __syncthreads();
            s->scanp[tid] = a * m;
            __syncthreads();
        }
        {
            unsigned long long key = s->skey[tid];
            float us = __uint_as_float((unsigned int)(key >> 32));
            unsigned int oi = (unsigned int)(key & 0xffffffffu);
            float excl = (tid == 0) ? 1.0f : s->scanp[tid - 1];
            s->alloc_[oi] = (1.0f - us) * excl;
        }
        __syncthreads();

        // P8: new write weights
        float wwsum;
        {
            float ag = s->allocg;
            float wwn = s->writeg * (ag * s->alloc_[tid] + (1.0f - ag) * s->wc[tid]);
            s->ww[tid] = wwn;
            wwsum = bsum(s->red, wwn, tid);
        }

        // P9: memory update + read-content sim on new mem
        {
            float wwn = s->ww[tid];
            float nrm = 0.f, d0 = 0.f, d1 = 0.f, d2 = 0.f, d3 = 0.f;
#pragma unroll 8
            for (int w = 0; w < Wn; ++w) {
                float m = s->mem[tid][w];
                float u2 = fmaf(wwn, s->wv[w], m);
                m = fmaf(-(wwn * s->er[w]), m, u2);
                s->mem[tid][w] = m;
                nrm = fmaf(m, m, nrm);
                float4 k4 = s->keyn4[w];
                d0 = fmaf(m, k4.x, d0); d1 = fmaf(m, k4.y, d1);
                d2 = fmaf(m, k4.z, d2); d3 = fmaf(m, k4.w, d3);
            }
            float inv = 1.0f / (sqrtf(nrm) + EPSf);
            s->rcv[tid] = make_float4(d0 * inv, d1 * inv, d2 * inv, d3 * inv);
        }
        __syncthreads();
        {   // read-content softmax over n, per r
            float4 rv = s->rcv[tid];
            float v[4] = {rv.x, rv.y, rv.z, rv.w};
            float m4[4] = {v[0], v[1], v[2], v[3]};
            bred4(s->red, m4, tid, 1);
#pragma unroll
            for (int r = 0; r < 4; ++r) v[r] = expf(v[r] - m4[r]);
            float s4[4] = {v[0], v[1], v[2], v[3]};
            bred4(s->red, s4, tid, 0);
            s->rcv[tid] = make_float4(v[0] / s4[0], v[1] / s4[1], v[2] / s4[2], v[3] / s4[3]);
        }

        // P10: link update (new ww, old prec) fused with bwd = L_new^T @ rw_old,
        //      column-parallel so global accesses are coalesced
        {
            int n = tid;
            float wwn = s->ww[n], prn = s->prec[n];
            float b0 = 0.f, b1a = 0.f, b2a = 0.f, b3 = 0.f;
#pragma unroll 4
            for (int m = 0; m < Nn; ++m) {
                float L = lk[m * Nn + n];
                float wm = s->ww[m];
                float Ln = fmaf(wm, prn, L);
                Ln = fmaf(-(wm + wwn), L, Ln);
                if (m == n) Ln = 0.f;
                lk[m * Nn + n] = Ln;
                float4 r4 = s->rwv[m];
                b0 = fmaf(Ln, r4.x, b0); b1a = fmaf(Ln, r4.y, b1a);
                b2a = fmaf(Ln, r4.z, b2a); b3 = fmaf(Ln, r4.w, b3);
            }
            s->bwdv[n] = make_float4(b0, b1a, b2a, b3);
            s->prec[n] = fmaf(1.0f - wwsum, prn, wwn);  // uses old prec read above
        }
        __syncthreads();

        // P11: fwd = L_new @ rw_old, staged 32-row tiles through shared
        for (int blk = 0; blk < 8; ++blk) {
            const float4* src = (const float4*)(lk + blk * 32 * Nn);
#pragma unroll
            for (int k = 0; k < 8; ++k) {
                int idx = tid + k * 256;
                s->Lst[(idx >> 6) * 65 + (idx & 63)] = src[idx];
            }
            __syncthreads();
            {
                int rloc = tid & 31, seg = tid >> 5;
                float a0 = 0.f, a1 = 0.f, a2 = 0.f, a3 = 0.f;
#pragma unroll
                for (int k4 = 0; k4 < 8; ++k4) {
                    float4 L4 = s->Lst[rloc * 65 + seg * 8 + k4];
                    int c0 = (seg * 8 + k4) * 4;
                    float4 ra = s->rwv[c0], rb = s->rwv[c0 + 1];
                    float4 rc_ = s->rwv[c0 + 2], rd = s->rwv[c0 + 3];
                    a0 = fmaf(L4.x, ra.x, a0); a1 = fmaf(L4.x, ra.y, a1);
                    a2 = fmaf(L4.x, ra.z, a2); a3 = fmaf(L4.x, ra.w, a3);
                    a0 = fmaf(L4.y, rb.x, a0); a1 = fmaf(L4.y, rb.y, a1);
                    a2 = fmaf(L4.y, rb.z, a2); a3 = fmaf(L4.y, rb.w, a3);
                    a0 = fmaf(L4.z, rc_.x, a0); a1 = fmaf(L4.z, rc_.y, a1);
                    a2 = fmaf(L4.z, rc_.z, a2); a3 = fmaf(L4.z, rc_.w, a3);
                    a0 = fmaf(L4.w, rd.x, a0); a1 = fmaf(L4.w, rd.y, a1);
                    a2 = fmaf(L4.w, rd.z, a2); a3 = fmaf(L4.w, rd.w, a3);
                }
                s->scratch4[rloc * 8 + seg] = make_float4(a0, a1, a2, a3);
            }
            __syncthreads();
            if (tid < 128) {
                int row = tid >> 2, r = tid & 3;
                float v = 0.f;
#pragma unroll
                for (int seg = 0; seg < 8; ++seg) v += sc[(row * 8 + seg) * 4 + r];
                ((float*)s->fwdv)[(blk * 32 + row) * 4 + r] = v;
            }
            __syncthreads();
        }

        // P12: new read weights
        {
            float4 bw = s->bwdv[tid], rc4 = s->rcv[tid], fw = s->fwdv[tid];
            float4 nrw;
            nrw.x = bw.x * s->modes[0][0] + rc4.x * s->modes[1][0] + fw.x * s->modes[2][0];
            nrw.y = bw.y * s->modes[0][1] + rc4.y * s->modes[1][1] + fw.y * s->modes[2][1];
            nrw.z = bw.z * s->modes[0][2] + rc4.z * s->modes[1][2] + fw.z * s->modes[2][2];
            nrw.w = bw.w * s->modes[0][3] + rc4.w * s->modes[1][3] + fw.w * s->modes[2][3];
            s->rwv[tid] = nrw;
        }
        __syncthreads();

        // P13: rvec[w][r] = sum_n mem[n][w] * rw[n][r]
        {
            int w = tid & 63, seg = tid >> 6;
            float a0 = 0.f, a1 = 0.f, a2 = 0.f, a3 = 0.f;
            int n0 = seg * 64;
#pragma unroll 4
            for (int n = n0; n < n0 + 64; ++n) {
                float m = s->mem[n][w];
                float4 r4 = s->rwv[n];
                a0 = fmaf(m, r4.x, a0); a1 = fmaf(m, r4.y, a1);
                a2 = fmaf(m, r4.z, a2); a3 = fmaf(m, r4.w, a3);
            }
            s->scratch4[tid] = make_float4(a0, a1, a2, a3);
        }
        __syncthreads();
        {
            int w = tid >> 2, r = tid & 3;
            float v = 0.f;
#pragma unroll
            for (int seg = 0; seg < 4; ++seg) v += sc[(seg * 64 + w) * 4 + r];
            s->rvec[w * 4 + r] = v;   // flat w*R+r matches (W,R) row-major reshape
        }
        __syncthreads();

        // P14: out = nn @ W_out + rvec @ W_mem_out
        {
            int o = tid & 63, seg = tid >> 6;
            float acc = 0.f;
            int j0 = seg * 64;
#pragma unroll 4
            for (int j = j0; j < j0 + 64; ++j) {
                acc = fmaf(s->nn[j], Wout[j * 64 + o], acc);
                acc = fmaf(s->rvec[j], Wmem[j * 64 + o], acc);
            }
            sc[seg * 64 + o] = acc;
        }
        __syncthreads();
        if (tid < 64) {
            out[(t * Bn + b) * 64 + tid] = sc[tid] + sc[64 + tid] + sc[128 + tid] + sc[192 + tid];
        }
        __syncthreads();
    }
}

extern "C" void kernel_launch(void* const* d_in, const int* in_sizes, int n_in,
                              void* d_out, int out_size) {
    (void)in_sizes; (void)n_in; (void)out_size;
    const float* x    = (const float*)d_in[0];
    const float* W1   = (const float*)d_in[1];
    const float* b1   = (const float*)d_in[2];
    const float* W2   = (const float*)d_in[3];
    const float* b2   = (const float*)d_in[4];
    const float* Wif  = (const float*)d_in[5];
    const float* bif  = (const float*)d_in[6];
    const float* Wout = (const float*)d_in[7];
    const float* Wmem = (const float*)d_in[8];
    float* out = (float*)d_out;

    cudaFuncSetAttribute(dnc_kernel, cudaFuncAttributeMaxDynamicSharedMemorySize,
                         (int)sizeof(SMem));
    repack_kernel<<<256, IFP>>>(Wif);
    dnc_kernel<<<Bn, NT, sizeof(SMem)>>>(x, W1, b1, W2, b2, bif, Wout, Wmem, out);
}

// round 6
// speedup vs baseline: 1.3291x; 1.3291x over previous
#include <cuda_runtime.h>
#include <math.h>

#define Tn   64
#define Bn   16
#define Nn   256
#define Wn   64
#define Rn   4
#define INn  64
#define IFS  471
#define IFP  472
#define EPSf 1e-6f
#define NT   256

// global scratch (allocation-free)
__device__ float g_link[Bn * Nn * Nn];   // 4 MB, L2-resident; lk[row*256+col]
__device__ float g_Wifp[256 * IFP];      // W_if repacked pitch 471 -> 472

struct SMem {
    float  mem[Nn][Wn + 1];          // pitch 65, conflict-free
    float4 Lst[32 * 65];             // staging tile (32 rows x pitch 260 floats)
    float4 scratch4[256];
    float4 fwdv[Nn];
    float4 bwdv[Nn];
    float4 rcv[Nn];
    float4 rwv[Nn];
    float4 keyn4[Wn];
    float  rvec[256];
    float  ctrl[INn + 256];
    float  h[256];
    float  nn[256];
    float  z[IFP];
    float  ww[Nn];
    float  prec[Nn];
    float  usage[Nn];
    float  alloc_[Nn];
    unsigned long long skey[Nn];
    float  wkeyn[Wn];
    float  er[Wn];
    float  wv[Wn];
    float  wc[Nn];
    float  red[40];
    float  rstr[Rn];
    float  freeg[Rn];
    float  modes[3][Rn];
    float  wstr, allocg, writeg;
};

__device__ __forceinline__ float sigm_(float x) { return 1.0f / (1.0f + expf(-x)); }
__device__ __forceinline__ float softp_(float x) { return fmaxf(x, 0.0f) + log1pf(expf(-fabsf(x))); }

__device__ __forceinline__ float bsum(float* red, float v, int tid) {
#pragma unroll
    for (int o = 16; o; o >>= 1) v += __shfl_xor_sync(0xffffffffu, v, o);
    if ((tid & 31) == 0) red[tid >> 5] = v;
    __syncthreads();
    if (tid == 0) {
        float a = red[0];
#pragma unroll
        for (int i = 1; i < 8; ++i) a += red[i];
        red[36] = a;
    }
    __syncthreads();
    return red[36];
}
__device__ __forceinline__ float bmax(float* red, float v, int tid) {
#pragma unroll
    for (int o = 16; o; o >>= 1) v = fmaxf(v, __shfl_xor_sync(0xffffffffu, v, o));
    if ((tid & 31) == 0) red[tid >> 5] = v;
    __syncthreads();
    if (tid == 0) {
        float a = red[0];
#pragma unroll
        for (int i = 1; i < 8; ++i) a = fmaxf(a, red[i]);
        red[36] = a;
    }
    __syncthreads();
    return red[36];
}
// 4-wide block reduction: v[0..3] replaced with block-reduced values
__device__ __forceinline__ void bred4(float* red, float* v, int tid, int domax) {
#pragma unroll
    for (int o = 16; o; o >>= 1) {
#pragma unroll
        for (int r = 0; r < 4; ++r) {
            float w = __shfl_xor_sync(0xffffffffu, v[r], o);
            v[r] = domax ? fmaxf(v[r], w) : (v[r] + w);
        }
    }
    if ((tid & 31) == 0) {
#pragma unroll
        for (int r = 0; r < 4; ++r) red[(tid >> 5) * 4 + r] = v[r];
    }
    __syncthreads();
    if (tid < 4) {
        float a = red[tid];
#pragma unroll
        for (int w = 1; w < 8; ++w) {
            float b = red[w * 4 + tid];
            a = domax ? fmaxf(a, b) : (a + b);
        }
        red[32 + tid] = a;
    }
    __syncthreads();
#pragma unroll
    for (int r = 0; r < 4; ++r) v[r] = red[32 + r];
}

__global__ void repack_kernel(const float* __restrict__ Wif) {
    int i = blockIdx.x;
    int j = threadIdx.x;
    if (j < IFP) g_Wifp[i * IFP + j] = (j < IFS) ? Wif[i * IFS + j] : 0.0f;
}

__global__ void __launch_bounds__(NT, 1)
dnc_kernel(const float* __restrict__ x, const float* __restrict__ W1,
           const float* __restrict__ b1, const float* __restrict__ W2,
           const float* __restrict__ b2, const float* __restrict__ bif,
           const float* __restrict__ Wout, const float* __restrict__ Wmem,
           float* __restrict__ out) {
    extern __shared__ char smraw[];
    SMem* s = (SMem*)smraw;
    const int tid = threadIdx.x;
    const int lane = tid & 31, warp = tid >> 5;
    const int b = blockIdx.x;
    float* lk = g_link + b * (Nn * Nn);

    // init carries
    {
        float4 z4 = make_float4(0.f, 0.f, 0.f, 0.f);
        for (int i = tid; i < Nn * Nn / 4; i += NT) ((float4*)lk)[i] = z4;
#pragma unroll 8
        for (int w = 0; w < Wn; ++w) s->mem[tid][w] = EPSf;
        s->usage[tid] = 0.0f;
        s->ww[tid] = 0.0f;
        s->prec[tid] = 0.0f;
        s->rwv[tid] = z4;
        s->rvec[tid] = 0.0f;
    }
    __syncthreads();

    float* sc = (float*)s->scratch4;
    float* lstf = (float*)s->Lst;

    for (int t = 0; t < Tn; ++t) {
        // P1: controller input
        if (tid < INn) s->ctrl[tid] = x[(t * Bn + b) * INn + tid];
        s->ctrl[INn + tid] = s->rvec[tid];
        __syncthreads();

        // P2: h = tanh(ctrl @ W1 + b1), 320x256
        {
            int sg = tid >> 6, q = tid & 63;
            const float4* Wp = (const float4*)W1;
            float4 acc = make_float4(0.f, 0.f, 0.f, 0.f);
            int i0 = sg * 80;
#pragma unroll 8
            for (int i = i0; i < i0 + 80; ++i) {
                float c = s->ctrl[i];
                float4 w4 = Wp[i * 64 + q];
                acc.x = fmaf(c, w4.x, acc.x); acc.y = fmaf(c, w4.y, acc.y);
                acc.z = fmaf(c, w4.z, acc.z); acc.w = fmaf(c, w4.w, acc.w);
            }
            s->scratch4[sg * 64 + q] = acc;
        }
        __syncthreads();
        {
            int q = tid >> 2, c = tid & 3;
            float v = b1[tid];
#pragma unroll
            for (int sg = 0; sg < 4; ++sg) v += sc[(sg * 64 + q) * 4 + c];
            s->h[tid] = tanhf(v);
        }
        __syncthreads();

        // P3: nn = tanh(h @ W2 + b2), 256x256
        {
            int sg = tid >> 6, q = tid & 63;
            const float4* Wp = (const float4*)W2;
            float4 acc = make_float4(0.f, 0.f, 0.f, 0.f);
            int i0 = sg * 64;
#pragma unroll 8
            for (int i = i0; i < i0 + 64; ++i) {
                float c = s->h[i];
                float4 w4 = Wp[i * 64 + q];
                acc.x = fmaf(c, w4.x, acc.x); acc.y = fmaf(c, w4.y, acc.y);
                acc.z = fmaf(c, w4.z, acc.z); acc.w = fmaf(c, w4.w, acc.w);
            }
            s->scratch4[sg * 64 + q] = acc;
        }
        __syncthreads();
        {
            int q = tid >> 2, c = tid & 3;
            float v = b2[tid];
#pragma unroll
            for (int sg = 0; sg < 4; ++sg) v += sc[(sg * 64 + q) * 4 + c];
            s->nn[tid] = tanhf(v);
        }
        __syncthreads();

        // P4: z = nn @ W_if + b_if, 256x471 (packed pitch 472)
        {   // round A: outputs 0..255
            int sg = tid >> 6, q = tid & 63;
            const float4* Wp = (const float4*)g_Wifp;
            float4 acc = make_float4(0.f, 0.f, 0.f, 0.f);
            int i0 = sg * 64;
#pragma unroll 8
            for (int i = i0; i < i0 + 64; ++i) {
                float c = s->nn[i];
                float4 w4 = Wp[i * 118 + q];
                acc.x = fmaf(c, w4.x, acc.x); acc.y = fmaf(c, w4.y, acc.y);
                acc.z = fmaf(c, w4.z, acc.z); acc.w = fmaf(c, w4.w, acc.w);
            }
            s->scratch4[sg * 64 + q] = acc;
        }
        __syncthreads();
        {
            int q = tid >> 2, c = tid & 3;
            float v = bif[tid];
#pragma unroll
            for (int sg = 0; sg < 4; ++sg) v += sc[(sg * 64 + q) * 4 + c];
            s->z[tid] = v;
        }
        __syncthreads();
        {   // round B: outputs 256..470
            int sg = tid >> 6, q0 = tid & 63;
            if (q0 < 54) {
                const float4* Wp = (const float4*)g_Wifp;
                float4 acc = make_float4(0.f, 0.f, 0.f, 0.f);
                int i0 = sg * 64, q = 64 + q0;
#pragma unroll 8
                for (int i = i0; i < i0 + 64; ++i) {
                    float c = s->nn[i];
                    float4 w4 = Wp[i * 118 + q];
                    acc.x = fmaf(c, w4.x, acc.x); acc.y = fmaf(c, w4.y, acc.y);
                    acc.z = fmaf(c, w4.z, acc.z); acc.w = fmaf(c, w4.w, acc.w);
                }
                s->scratch4[sg * 64 + q0] = acc;
            }
        }
        __syncthreads();
        if (tid < 215) {
            int j = 256 + tid;
            int qb = (j >> 2) - 64, c = j & 3;
            float v = bif[j];
#pragma unroll
            for (int sg = 0; sg < 4; ++sg) v += sc[(sg * 64 + qb) * 4 + c];
            s->z[j] = v;
        }
        __syncthreads();

        // P5: parse interface
        if (tid < Rn) s->rstr[tid] = 1.0f + softp_(s->z[256 + tid]);
        if (tid >= 4 && tid < 8) s->freeg[tid - 4] = sigm_(s->z[453 + (tid - 4)]);
        if (tid == 8)  s->wstr   = 1.0f + softp_(s->z[324]);
        if (tid == 9)  s->allocg = sigm_(s->z[457]);
        if (tid == 10) s->writeg = sigm_(s->z[458]);
        if (tid >= 64 && tid < 128) {
            int w = tid - 64;
            s->er[w] = sigm_(s->z[325 + w]);
            s->wv[w] = s->z[389 + w];
        }
        if (tid >= 16 && tid < 20) {
            int r = tid - 16;
            float s2 = 0.f;
#pragma unroll 8
            for (int w = 0; w < Wn; ++w) { float v = s->z[w * 4 + r]; s2 = fmaf(v, v, s2); }
            s->red[32 + r] = 1.0f / (sqrtf(s2) + EPSf);
        }
        if (tid == 20) {
            float s2 = 0.f;
#pragma unroll 8
            for (int w = 0; w < Wn; ++w) { float v = s->z[260 + w]; s2 = fmaf(v, v, s2); }
            s->red[38] = 1.0f / (sqrtf(s2) + EPSf);
        }
        if (tid >= 24 && tid < 28) {
            int r = tid - 24;
            float a = s->z[459 + r], bm = s->z[463 + r], c = s->z[467 + r];
            float mx = fmaxf(a, fmaxf(bm, c));
            float ea = expf(a - mx), eb = expf(bm - mx), ec = expf(c - mx);
            float si = 1.0f / (ea + eb + ec);
            s->modes[0][r] = ea * si; s->modes[1][r] = eb * si; s->modes[2][r] = ec * si;
        }
        __syncthreads();
        ((float*)s->keyn4)[tid] = s->z[tid] * s->red[32 + (tid & 3)] * s->rstr[tid & 3];
        if (tid < Wn) s->wkeyn[tid] = s->z[260 + tid] * s->red[38] * s->wstr;
        __syncthreads();

        // P6: retention + usage (old ww, old rw) + write-content sim (old mem)
        {
            float4 rw4 = s->rwv[tid];
            float ret = (1.f - s->freeg[0] * rw4.x) * (1.f - s->freeg[1] * rw4.y) *
                        (1.f - s->freeg[2] * rw4.z) * (1.f - s->freeg[3] * rw4.w);
            float u = s->usage[tid], w0 = s->ww[tid];
            u = (u + w0 - u * w0) * ret;
            s->usage[tid] = u;
            s->skey[tid] = ((unsigned long long)__float_as_uint(u) << 32) | (unsigned int)tid;
            float nrm = 0.f, dot = 0.f;
#pragma unroll 8
            for (int w = 0; w < Wn; ++w) {
                float m = s->mem[tid][w];
                nrm = fmaf(m, m, nrm);
                dot = fmaf(m, s->wkeyn[w], dot);
            }
            s->wc[tid] = dot / (sqrtf(nrm) + EPSf);
        }
        __syncthreads();
        {   // write-content softmax over n
            float v = s->wc[tid];
            float mx = bmax(s->red, v, tid);
            float e = expf(v - mx);
            float sm = bsum(s->red, e, tid);
            s->wc[tid] = e / sm;
        }

        // P7: allocation — hybrid bitonic sort (shfl intra-warp, shared cross-warp)
        {
            unsigned long long key = s->skey[tid];
            for (int k = 2; k <= 256; k <<= 1) {
                for (int j = k >> 1; j > 0; j >>= 1) {
                    bool up = ((tid & k) == 0);
                    bool keepmin = (((tid & j) == 0) == up);
                    if (j >= 32) {
                        s->skey[tid] = key;
                        __syncthreads();
                        unsigned long long other = s->skey[tid ^ j];
                        key = keepmin ? (key < other ? key : other)
                                      : (key < other ? other : key);
                        __syncthreads();
                    } else {
                        unsigned long long other = __shfl_xor_sync(0xffffffffu, key, j);
                        key = keepmin ? (key < other ? key : other)
                                      : (key < other ? other : key);
                    }
                }
            }
            // key = sorted (usage,idx) at position tid
            float us = __uint_as_float((unsigned int)(key >> 32));
            // inclusive product scan of sorted usage via warp shuffles
            float v = us;
#pragma unroll
            for (int o = 1; o < 32; o <<= 1) {
                float p = __shfl_up_sync(0xffffffffu, v, o);
                if (lane >= o) v *= p;
            }
            if (lane == 31) s->red[warp] = v;
            __syncthreads();
            if (tid == 0) {
                float p = 1.0f;
#pragma unroll
                for (int w = 0; w < 8; ++w) { s->red[8 + w] = p; p *= s->red[w]; }
            }
            __syncthreads();
            float wpre = s->red[8 + warp];
            v *= wpre;                                  // global inclusive product
            float p = __shfl_up_sync(0xffffffffu, v, 1);
            float excl = (lane == 0) ? wpre : p;        // exclusive product
            unsigned int oi = (unsigned int)(key & 0xffffffffu);
            s->alloc_[oi] = (1.0f - us) * excl;
        }
        __syncthreads();

        // P8: new write weights
        float wwsum;
        {
            float ag = s->allocg;
            float wwn = s->writeg * (ag * s->alloc_[tid] + (1.0f - ag) * s->wc[tid]);
            s->ww[tid] = wwn;
            wwsum = bsum(s->red, wwn, tid);
        }

        // P9: memory update + read-content sim on new mem
        {
            float wwn = s->ww[tid];
            float nrm = 0.f, d0 = 0.f, d1 = 0.f, d2 = 0.f, d3 = 0.f;
#pragma unroll 8
            for (int w = 0; w < Wn; ++w) {
                float m = s->mem[tid][w];
                float u2 = fmaf(wwn, s->wv[w], m);
                m = fmaf(-(wwn * s->er[w]), m, u2);
                s->mem[tid][w] = m;
                nrm = fmaf(m, m, nrm);
                float4 k4 = s->keyn4[w];
                d0 = fmaf(m, k4.x, d0); d1 = fmaf(m, k4.y, d1);
                d2 = fmaf(m, k4.z, d2); d3 = fmaf(m, k4.w, d3);
            }
            float inv = 1.0f / (sqrtf(nrm) + EPSf);
            s->rcv[tid] = make_float4(d0 * inv, d1 * inv, d2 * inv, d3 * inv);
        }
        __syncthreads();
        {   // read-content softmax over n, per r
            float4 rv = s->rcv[tid];
            float v[4] = {rv.x, rv.y, rv.z, rv.w};
            float m4[4] = {v[0], v[1], v[2], v[3]};
            bred4(s->red, m4, tid, 1);
#pragma unroll
            for (int r = 0; r < 4; ++r) v[r] = expf(v[r] - m4[r]);
            float s4[4] = {v[0], v[1], v[2], v[3]};
            bred4(s->red, s4, tid, 0);
            s->rcv[tid] = make_float4(v[0] / s4[0], v[1] / s4[1], v[2] / s4[2], v[3] / s4[3]);
        }

        // P10: fused link update + bwd (column pass) + fwd (staged tile row pass).
        // Each 32-row tile of L_new is staged into shared during the column
        // update, so fwd never re-reads the link matrix from L2.
        {
            float wwn = s->ww[tid], prn = s->prec[tid];
            float b0 = 0.f, b1a = 0.f, b2a = 0.f, b3 = 0.f;
            for (int tile = 0; tile < 8; ++tile) {
                int m0 = tile * 32;
#pragma unroll 8
                for (int ml = 0; ml < 32; ++ml) {
                    int m = m0 + ml;
                    float L = lk[m * Nn + tid];
                    float wm = s->ww[m];
                    float Ln = fmaf(wm, prn, L);
                    Ln = fmaf(-(wm + wwn), L, Ln);
                    if (m == tid) Ln = 0.f;
                    lk[m * Nn + tid] = Ln;
                    lstf[ml * 260 + tid] = Ln;
                    float4 r4 = s->rwv[m];
                    b0 = fmaf(Ln, r4.x, b0); b1a = fmaf(Ln, r4.y, b1a);
                    b2a = fmaf(Ln, r4.z, b2a); b3 = fmaf(Ln, r4.w, b3);
                }
                __syncthreads();
                {   // fwd partials for rows m0..m0+31 from the shared tile
                    int rloc = tid & 31, seg = tid >> 5;
                    float a0 = 0.f, a1 = 0.f, a2 = 0.f, a3 = 0.f;
#pragma unroll
                    for (int k4 = 0; k4 < 8; ++k4) {
                        float4 L4 = s->Lst[rloc * 65 + seg * 8 + k4];
                        int c0 = (seg * 8 + k4) * 4;
                        float4 ra = s->rwv[c0], rb = s->rwv[c0 + 1];
                        float4 rc_ = s->rwv[c0 + 2], rd = s->rwv[c0 + 3];
                        a0 = fmaf(L4.x, ra.x, a0); a1 = fmaf(L4.x, ra.y, a1);
                        a2 = fmaf(L4.x, ra.z, a2); a3 = fmaf(L4.x, ra.w, a3);
                        a0 = fmaf(L4.y, rb.x, a0); a1 = fmaf(L4.y, rb.y, a1);
                        a2 = fmaf(L4.y, rb.z, a2); a3 = fmaf(L4.y, rb.w, a3);
                        a0 = fmaf(L4.z, rc_.x, a0); a1 = fmaf(L4.z, rc_.y, a1);
                        a2 = fmaf(L4.z, rc_.z, a2); a3 = fmaf(L4.z, rc_.w, a3);
                        a0 = fmaf(L4.w, rd.x, a0); a1 = fmaf(L4.w, rd.y, a1);
                        a2 = fmaf(L4.w, rd.z, a2); a3 = fmaf(L4.w, rd.w, a3);
                    }
                    s->scratch4[rloc * 8 + seg] = make_float4(a0, a1, a2, a3);
                }
                __syncthreads();
                if (tid < 128) {
                    int row = tid >> 2, r = tid & 3;
                    float v = 0.f;
#pragma unroll
                    for (int seg = 0; seg < 8; ++seg) v += sc[(row * 8 + seg) * 4 + r];
                    ((float*)s->fwdv)[(m0 + row) * 4 + r] = v;
                }
                // no barrier: scratch4 is next written only after the next
                // tile's post-column-loop __syncthreads
            }
            s->bwdv[tid] = make_float4(b0, b1a, b2a, b3);
            s->prec[tid] = fmaf(1.0f - wwsum, prn, wwn);
        }
        __syncthreads();

        // P12: new read weights
        {
            float4 bw = s->bwdv[tid], rc4 = s->rcv[tid], fw = s->fwdv[tid];
            float4 nrw;
            nrw.x = bw.x * s->modes[0][0] + rc4.x * s->modes[1][0] + fw.x * s->modes[2][0];
            nrw.y = bw.y * s->modes[0][1] + rc4.y * s->modes[1][1] + fw.y * s->modes[2][1];
            nrw.z = bw.z * s->modes[0][2] + rc4.z * s->modes[1][2] + fw.z * s->modes[2][2];
            nrw.w = bw.w * s->modes[0][3] + rc4.w * s->modes[1][3] + fw.w * s->modes[2][3];
            s->rwv[tid] = nrw;
        }
        __syncthreads();

        // P13: rvec[w][r] = sum_n mem[n][w] * rw[n][r]
        {
            int w = tid & 63, seg = tid >> 6;
            float a0 = 0.f, a1 = 0.f, a2 = 0.f, a3 = 0.f;
            int n0 = seg * 64;
#pragma unroll 8
            for (int n = n0; n < n0 + 64; ++n) {
                float m = s->mem[n][w];
                float4 r4 = s->rwv[n];
                a0 = fmaf(m, r4.x, a0); a1 = fmaf(m, r4.y, a1);
                a2 = fmaf(m, r4.z, a2); a3 = fmaf(m, r4.w, a3);
            }
            s->scratch4[tid] = make_float4(a0, a1, a2, a3);
        }
        __syncthreads();
        {
            int w = tid >> 2, r = tid & 3;
            float v = 0.f;
#pragma unroll
            for (int seg = 0; seg < 4; ++seg) v += sc[(seg * 64 + w) * 4 + r];
            s->rvec[w * 4 + r] = v;
        }
        __syncthreads();

        // P14: out = nn @ W_out + rvec @ W_mem_out
        {
            int o = tid & 63, seg = tid >> 6;
            float acc = 0.f;
            int j0 = seg * 64;
#pragma unroll 8
            for (int j = j0; j < j0 + 64; ++j) {
                acc = fmaf(s->nn[j], Wout[j * 64 + o], acc);
                acc = fmaf(s->rvec[j], Wmem[j * 64 + o], acc);
            }
            sc[seg * 64 + o] = acc;
        }
        __syncthreads();
        if (tid < 64) {
            out[(t * Bn + b) * 64 + tid] = sc[tid] + sc[64 + tid] + sc[128 + tid] + sc[192 + tid];
        }
        __syncthreads();
    }
}

extern "C" void kernel_launch(void* const* d_in, const int* in_sizes, int n_in,
                              void* d_out, int out_size) {
    (void)in_sizes; (void)n_in; (void)out_size;
    const float* x    = (const float*)d_in[0];
    const float* W1   = (const float*)d_in[1];
    const float* b1   = (const float*)d_in[2];
    const float* W2   = (const float*)d_in[3];
    const float* b2   = (const float*)d_in[4];
    const float* Wif  = (const float*)d_in[5];
    const float* bif  = (const float*)d_in[6];
    const float* Wout = (const float*)d_in[7];
    const float* Wmem = (const float*)d_in[8];
    float* out = (float*)d_out;

    cudaFuncSetAttribute(dnc_kernel, cudaFuncAttributeMaxDynamicSharedMemorySize,
                         (int)sizeof(SMem));
    repack_kernel<<<256, IFP>>>(Wif);
    dnc_kernel<<<Bn, NT, sizeof(SMem)>>>(x, W1, b1, W2, b2, bif, Wout, Wmem, out);
}